// round 9
// baseline (speedup 1.0000x reference)
#include <cuda_runtime.h>
#include <mma.h>
#include <cuda_fp16.h>
#include <math.h>
#include <stdint.h>

using namespace nvcuda;

#define B_  32
#define N_  512
#define D_  512
#define H_  8
#define DK_ 64

// fp16 scratch (allocation-free rule: __device__ globals)
__device__ __half g_xh [B_*N_*D_];
__device__ __half g_wh [4*D_*D_];
__device__ __half g_qh [B_*H_*N_*DK_];
__device__ __half g_kh [B_*H_*N_*DK_];
__device__ __half g_vh [B_*H_*N_*DK_];
__device__ __half g_ctxh[B_*N_*D_];

__device__ __forceinline__ void st_half4(__half* p, float4 v) {
    __half2 a = __floats2half2_rn(v.x, v.y);
    __half2 b = __floats2half2_rn(v.z, v.w);
    uint2 u;
    u.x = *reinterpret_cast<uint32_t*>(&a);
    u.y = *reinterpret_cast<uint32_t*>(&b);
    *reinterpret_cast<uint2*>(p) = u;
}
__device__ __forceinline__ uint32_t smem_u32(const void* p) {
    uint32_t a;
    asm("{ .reg .u64 t; cvta.to.shared.u64 t, %1; cvt.u32.u64 %0, t; }" : "=r"(a) : "l"(p));
    return a;
}
#define CP_ASYNC16(dst, src) \
    asm volatile("cp.async.cg.shared.global [%0], [%1], 16;" :: "r"(dst), "l"(src))
#define CP_COMMIT() asm volatile("cp.async.commit_group;" ::: "memory")
#define CP_WAIT0()  asm volatile("cp.async.wait_group 0;" ::: "memory")
#define CP_WAIT1()  asm volatile("cp.async.wait_group 1;" ::: "memory")

// ---------------------------------------------------------------------------
// Prepass: convert x and the four weight matrices to fp16 once.
// ---------------------------------------------------------------------------
__global__ void conv_half(const float* __restrict__ x,
                          const float* __restrict__ Wq, const float* __restrict__ Wk,
                          const float* __restrict__ Wv, const float* __restrict__ Wo)
{
    const int XF4 = (B_ * N_ * D_) / 4;
    const int WF4 = (D_ * D_) / 4;
    const int i = blockIdx.x * blockDim.x + threadIdx.x;
    if (i < XF4) {
        st_half4(&g_xh[i * 4], reinterpret_cast<const float4*>(x)[i]);
    } else if (i < XF4 + 4 * WF4) {
        const int j = i - XF4;
        const int sel = j >> 16;
        const int off = j & (WF4 - 1);
        const float* W = sel == 0 ? Wq : sel == 1 ? Wk : sel == 2 ? Wv : Wo;
        st_half4(&g_wh[sel * D_ * D_ + off * 4],
                 reinterpret_cast<const float4*>(W)[off]);
    }
}

// ---------------------------------------------------------------------------
// fp16 wmma GEMM, 128 thr = 4 warps, warp tile 64x64, BK=64 (8 iterations),
// 3-stage cp.async pipeline. Epilogue stage aliases the buffers.
// ---------------------------------------------------------------------------
#define GLDH 72                               // half leading dim (144B rows)
#define ABYT (128 * GLDH * 2)                 // 18432 B per matrix per stage
#define STGB (2 * ABYT)                       // 36864 B per stage (A+B)
#define GEMM_SMEM (3 * STGB)                  // 110592 B; >= stage 128*132*4

template<int MODE>
__global__ __launch_bounds__(128, 2) void gemm_hc(
    const float* __restrict__ b0, const float* __restrict__ b1,
    const float* __restrict__ b2, float* __restrict__ outflat)
{
    extern __shared__ char smc[];
    float* stage = reinterpret_cast<float*>(smc);     // [128][132], epilogue only

    const int z = blockIdx.z;
    const __half* __restrict__ Ap = (MODE == 0) ? g_xh : g_ctxh;
    const __half* __restrict__ Wp = g_wh + (size_t)((MODE == 0) ? z : 3) * D_ * D_;
    const float*  __restrict__ bp = (MODE == 0) ? (z == 0 ? b0 : (z == 1 ? b1 : b2)) : b0;

    const int tid = threadIdx.x;
    const int w  = tid >> 5;
    const int wr = w >> 1;
    const int wc = w & 1;
    const int m0 = blockIdx.y * 128;
    const int n0 = blockIdx.x * 128;

    wmma::fragment<wmma::accumulator, 16, 16, 16, float> acc[4][4];
    #pragma unroll
    for (int mi = 0; mi < 4; mi++)
        #pragma unroll
        for (int ni = 0; ni < 4; ni++)
            wmma::fill_fragment(acc[mi][ni], 0.0f);

    // loader: thread owns one 128-B row slice per matrix per chunk (8 x 16B)
    const __half* arow = Ap + (size_t)(m0 + tid) * D_;
    const __half* brow = Wp + (size_t)(n0 + tid) * D_;
    uint32_t dA[3], dB[3];
    #pragma unroll
    for (int s = 0; s < 3; s++) {
        dA[s] = smem_u32(smc + s * STGB) + tid * (GLDH * 2);
        dB[s] = smem_u32(smc + s * STGB + ABYT) + tid * (GLDH * 2);
    }

    // prologue: chunks 0,1 -> stages 0,1
    #pragma unroll
    for (int pc = 0; pc < 2; pc++) {
        #pragma unroll
        for (int c = 0; c < 8; c++) {
            CP_ASYNC16(dA[pc] + c * 16, arow + pc * 64 + c * 8);
            CP_ASYNC16(dB[pc] + c * 16, brow + pc * 64 + c * 8);
        }
        CP_COMMIT();
    }

    #pragma unroll 1
    for (int it = 0; it < 8; it++) {
        if (it == 7) { CP_WAIT0(); } else { CP_WAIT1(); }
        __syncthreads();

        if (it + 2 < 8) {
            const int s = (it + 2) % 3;
            const int kn = (it + 2) * 64;
            #pragma unroll
            for (int c = 0; c < 8; c++) {
                CP_ASYNC16(dA[s] + c * 16, arow + kn + c * 8);
                CP_ASYNC16(dB[s] + c * 16, brow + kn + c * 8);
            }
            CP_COMMIT();
        }

        const int cs = it % 3;
        const __half* bA = reinterpret_cast<const __half*>(smc + cs * STGB);
        const __half* bB = reinterpret_cast<const __half*>(smc + cs * STGB + ABYT);
        #pragma unroll
        for (int ks = 0; ks < 4; ks++) {
            wmma::fragment<wmma::matrix_a, 16, 16, 16, __half, wmma::row_major> af[4];
            wmma::fragment<wmma::matrix_b, 16, 16, 16, __half, wmma::col_major> bf[4];
            #pragma unroll
            for (int mi = 0; mi < 4; mi++)
                wmma::load_matrix_sync(af[mi], &bA[(wr * 64 + mi * 16) * GLDH + ks * 16], GLDH);
            #pragma unroll
            for (int ni = 0; ni < 4; ni++)
                wmma::load_matrix_sync(bf[ni], &bB[(wc * 64 + ni * 16) * GLDH + ks * 16], GLDH);
            #pragma unroll
            for (int mi = 0; mi < 4; mi++)
                #pragma unroll
                for (int ni = 0; ni < 4; ni++)
                    wmma::mma_sync(acc[mi][ni], af[mi], bf[ni], acc[mi][ni]);
        }
    }

    __syncthreads();   // computes done before stage overwrites buffers
    #pragma unroll
    for (int mi = 0; mi < 4; mi++)
        #pragma unroll
        for (int ni = 0; ni < 4; ni++)
            wmma::store_matrix_sync(&stage[(wr * 64 + mi * 16) * 132 + wc * 64 + ni * 16],
                                    acc[mi][ni], 132, wmma::mem_row_major);
    __syncthreads();

    const float scale = (MODE == 0 && z == 0) ? 0.125f : 1.0f;
    __half* dstH = (MODE == 0) ? (z == 0 ? g_qh : (z == 1 ? g_kh : g_vh)) : nullptr;

    for (int s = tid; s < 128 * 32; s += 128) {
        const int r  = s >> 5;
        const int c4 = s & 31;
        float4 v = *reinterpret_cast<const float4*>(&stage[r * 132 + c4 * 4]);
        const float4 bb = *reinterpret_cast<const float4*>(&bp[n0 + c4 * 4]);
        v.x = (v.x + bb.x) * scale;
        v.y = (v.y + bb.y) * scale;
        v.z = (v.z + bb.z) * scale;
        v.w = (v.w + bb.w) * scale;
        const int m = m0 + r;
        const int n = n0 + c4 * 4;
        if (MODE == 0) {
            const int batch = m >> 9;
            const int nn    = m & 511;
            const int h     = n >> 6;
            const int dk    = n & 63;
            st_half4(&dstH[(((size_t)batch * H_ + h) * N_ + nn) * DK_ + dk], v);
        } else {
            *reinterpret_cast<float4*>(&outflat[(size_t)m * D_ + n]) = v;
        }
    }
}

// ---------------------------------------------------------------------------
// Attention, fp16 wmma, shifted softmax (exact: constant shift cancels).
// O accumulator persists in register fragments; l-sum in thread registers.
// K/V double-buffered via cp.async. 4 barriers/tile. (unchanged, round 8)
// ---------------------------------------------------------------------------
#define SLD 68
#define HLD 72
#define KVH (64 * HLD)
#define ATTN_SMEM ((64*SLD + 128) * 4 + 6 * KVH * 2)   // 73216

__global__ __launch_bounds__(256, 2) void attn_hc(
    const float* __restrict__ dist, const float* __restrict__ dw)
{
    extern __shared__ float sm[];
    float* Sf  = sm;                              // [64][SLD] scores / final O
    float* l_s = Sf + 64 * SLD;                   // [64]
    float* dws = l_s + 64;                        // [21..64]
    __half* Qs  = reinterpret_cast<__half*>(dws + 64);
    __half* Ps  = Qs + KVH;
    __half* Kb0 = Ps + KVH;
    __half* Vb0 = Kb0 + KVH;
    __half* Kb1 = Vb0 + KVH;
    __half* Vb1 = Kb1 + KVH;

    const int b  = blockIdx.z;
    const int h  = blockIdx.y;
    const int qt = blockIdx.x;
    const int tid = threadIdx.x;
    const int w  = tid >> 5;
    const int wm = w >> 1;
    const int wn = w & 1;
    const int q0 = qt * 64;
    const size_t base = ((size_t)b * H_ + h) * (size_t)N_ * DK_;

    if (tid < 21) dws[tid] = dw[tid];

    const uint32_t kd[2] = { smem_u32(Kb0), smem_u32(Kb1) };
    const uint32_t vd[2] = { smem_u32(Vb0), smem_u32(Vb1) };
    const int lrow0 = tid >> 3, lseg0 = tid & 7;
    const int lrow1 = (tid + 256) >> 3, lseg1 = tid & 7;

    {
        const __half* kg = g_kh + base;
        const __half* vg = g_vh + base;
        CP_ASYNC16(kd[0] + lrow0 * 144 + lseg0 * 16, kg + lrow0 * DK_ + lseg0 * 8);
        CP_ASYNC16(kd[0] + lrow1 * 144 + lseg1 * 16, kg + lrow1 * DK_ + lseg1 * 8);
        CP_ASYNC16(vd[0] + lrow0 * 144 + lseg0 * 16, vg + lrow0 * DK_ + lseg0 * 8);
        CP_ASYNC16(vd[0] + lrow1 * 144 + lseg1 * 16, vg + lrow1 * DK_ + lseg1 * 8);
        CP_COMMIT();
    }

    for (int s = tid; s < 64 * 16; s += 256) {
        const int r  = s >> 4;
        const int c4 = s & 15;
        *reinterpret_cast<uint2*>(&Qs[r * HLD + c4 * 4]) =
            *reinterpret_cast<const uint2*>(&g_qh[base + (size_t)(q0 + r) * DK_ + c4 * 4]);
    }
    __syncthreads();

    wmma::fragment<wmma::matrix_a, 16, 16, 16, __half, wmma::row_major> qf[4];
    #pragma unroll
    for (int d = 0; d < 4; d++)
        wmma::load_matrix_sync(qf[d], &Qs[(wm * 16) * HLD + d * 16], HLD);

    wmma::fragment<wmma::accumulator, 16, 16, 16, float> cacc[2];
    #pragma unroll
    for (int ni = 0; ni < 2; ni++) wmma::fill_fragment(cacc[ni], 0.0f);

    const int sr = tid >> 2;
    const int sp = tid & 3;
    float lsum = 0.0f;

    #pragma unroll 1
    for (int kt = 0; kt < 8; kt++) {
        CP_WAIT0();
        __syncthreads();

        if (kt + 1 < 8) {
            const int nb = (kt + 1) & 1;
            const __half* kg = g_kh + base + (size_t)(kt + 1) * 64 * DK_;
            const __half* vg = g_vh + base + (size_t)(kt + 1) * 64 * DK_;
            CP_ASYNC16(kd[nb] + lrow0 * 144 + lseg0 * 16, kg + lrow0 * DK_ + lseg0 * 8);
            CP_ASYNC16(kd[nb] + lrow1 * 144 + lseg1 * 16, kg + lrow1 * DK_ + lseg1 * 8);
            CP_ASYNC16(vd[nb] + lrow0 * 144 + lseg0 * 16, vg + lrow0 * DK_ + lseg0 * 8);
            CP_ASYNC16(vd[nb] + lrow1 * 144 + lseg1 * 16, vg + lrow1 * DK_ + lseg1 * 8);
            CP_COMMIT();
        }

        const __half* Ks = (kt & 1) ? Kb1 : Kb0;
        const __half* Vs = (kt & 1) ? Vb1 : Vb0;

        // S = Q K^T -> Sf
        {
            wmma::fragment<wmma::accumulator, 16, 16, 16, float> sacc[2];
            #pragma unroll
            for (int ni = 0; ni < 2; ni++) wmma::fill_fragment(sacc[ni], 0.0f);
            #pragma unroll
            for (int d = 0; d < 4; d++) {
                wmma::fragment<wmma::matrix_b, 16, 16, 16, __half, wmma::col_major> bf[2];
                #pragma unroll
                for (int ni = 0; ni < 2; ni++)
                    wmma::load_matrix_sync(bf[ni], &Ks[(wn * 32 + ni * 16) * HLD + d * 16], HLD);
                #pragma unroll
                for (int ni = 0; ni < 2; ni++)
                    wmma::mma_sync(sacc[ni], qf[d], bf[ni], sacc[ni]);
            }
            #pragma unroll
            for (int ni = 0; ni < 2; ni++)
                wmma::store_matrix_sync(&Sf[(wm * 16) * SLD + wn * 32 + ni * 16],
                                        sacc[ni], SLD, wmma::mem_row_major);
        }
        __syncthreads();

        // P = exp(s + bias - 2)
        {
            const float* __restrict__ drow =
                &dist[((size_t)b * N_ + (q0 + sr)) * N_ + kt * 64 + sp * 16];
            #pragma unroll
            for (int i4 = 0; i4 < 4; i4++) {
                const float4 dd = *reinterpret_cast<const float4*>(&drow[i4 * 4]);
                const float4 ss = *reinterpret_cast<const float4*>(&Sf[sr * SLD + sp * 16 + i4 * 4]);
                int t0 = (int)(dd.x * 0.2f); t0 = t0 < 0 ? 0 : (t0 > 20 ? 20 : t0);
                int t1 = (int)(dd.y * 0.2f); t1 = t1 < 0 ? 0 : (t1 > 20 ? 20 : t1);
                int t2 = (int)(dd.z * 0.2f); t2 = t2 < 0 ? 0 : (t2 > 20 ? 20 : t2);
                int t3 = (int)(dd.w * 0.2f); t3 = t3 < 0 ? 0 : (t3 > 20 ? 20 : t3);
                float4 e;
                e.x = __expf(ss.x + dws[t0] - 2.0f);
                e.y = __expf(ss.y + dws[t1] - 2.0f);
                e.z = __expf(ss.z + dws[t2] - 2.0f);
                e.w = __expf(ss.w + dws[t3] - 2.0f);
                __half2 h0 = __floats2half2_rn(e.x, e.y);
                __half2 h1 = __floats2half2_rn(e.z, e.w);
                uint2 u;
                u.x = *reinterpret_cast<uint32_t*>(&h0);
                u.y = *reinterpret_cast<uint32_t*>(&h1);
                *reinterpret_cast<uint2*>(&Ps[sr * HLD + sp * 16 + i4 * 4]) = u;
                const float2 f0 = __half22float2(h0);
                const float2 f1 = __half22float2(h1);
                lsum += (f0.x + f0.y) + (f1.x + f1.y);
            }
        }
        __syncthreads();

        // O += P @ V
        #pragma unroll
        for (int ks = 0; ks < 4; ks++) {
            wmma::fragment<wmma::matrix_a, 16, 16, 16, __half, wmma::row_major> pf;
            wmma::load_matrix_sync(pf, &Ps[(wm * 16) * HLD + ks * 16], HLD);
            wmma::fragment<wmma::matrix_b, 16, 16, 16, __half, wmma::row_major> vf[2];
            #pragma unroll
            for (int ni = 0; ni < 2; ni++)
                wmma::load_matrix_sync(vf[ni], &Vs[(ks * 16) * HLD + wn * 32 + ni * 16], HLD);
            #pragma unroll
            for (int ni = 0; ni < 2; ni++)
                wmma::mma_sync(cacc[ni], pf, vf[ni], cacc[ni]);
        }
        __syncthreads();
    }

    lsum += __shfl_xor_sync(0xffffffffu, lsum, 1, 4);
    lsum += __shfl_xor_sync(0xffffffffu, lsum, 2, 4);
    if (sp == 0) l_s[sr] = lsum;

    #pragma unroll
    for (int ni = 0; ni < 2; ni++)
        wmma::store_matrix_sync(&Sf[(wm * 16) * SLD + wn * 32 + ni * 16],
                                cacc[ni], SLD, wmma::mem_row_major);
    __syncthreads();

    for (int s = tid; s < 64 * 16; s += 256) {
        const int r  = s >> 4;
        const int c4 = s & 15;
        const float inv = 1.0f / l_s[r];
        float4 o = *reinterpret_cast<const float4*>(&Sf[r * SLD + c4 * 4]);
        o.x *= inv; o.y *= inv; o.z *= inv; o.w *= inv;
        st_half4(&g_ctxh[((size_t)b * N_ + (q0 + r)) * D_ + h * 64 + c4 * 4], o);
    }
}

// ---------------------------------------------------------------------------
extern "C" void kernel_launch(void* const* d_in, const int* in_sizes, int n_in,
                              void* d_out, int out_size)
{
    const float* x    = (const float*)d_in[0];
    const float* dist = (const float*)d_in[1];
    const float* Wq   = (const float*)d_in[2];
    const float* bq   = (const float*)d_in[3];
    const float* Wk   = (const float*)d_in[4];
    const float* bk   = (const float*)d_in[5];
    const float* Wv   = (const float*)d_in[6];
    const float* bv   = (const float*)d_in[7];
    const float* Wo   = (const float*)d_in[8];
    const float* bo   = (const float*)d_in[9];
    const float* dw   = (const float*)d_in[10];
    float* out = (float*)d_out;

    cudaFuncSetAttribute(gemm_hc<0>, cudaFuncAttributeMaxDynamicSharedMemorySize, GEMM_SMEM);
    cudaFuncSetAttribute(gemm_hc<1>, cudaFuncAttributeMaxDynamicSharedMemorySize, GEMM_SMEM);
    cudaFuncSetAttribute(attn_hc,    cudaFuncAttributeMaxDynamicSharedMemorySize, ATTN_SMEM);

    const int convN = (B_*N_*D_)/4 + 4 * (D_*D_)/4;
    conv_half<<<(convN + 255) / 256, 256>>>(x, Wq, Wk, Wv, Wo);

    dim3 gridQKV(D_ / 128, (B_ * N_) / 128, 3);
    gemm_hc<0><<<gridQKV, 128, GEMM_SMEM>>>(bq, bk, bv, nullptr);

    dim3 gridAttn(N_ / 64, H_, B_);
    attn_hc<<<gridAttn, 256, ATTN_SMEM>>>(dist, dw);

    dim3 gridO(D_ / 128, (B_ * N_) / 128, 1);
    gemm_hc<1><<<gridO, 128, GEMM_SMEM>>>(bo, nullptr, nullptr, out);
}

// round 10
// speedup vs baseline: 1.0753x; 1.0753x over previous
#include <cuda_runtime.h>
#include <mma.h>
#include <cuda_fp16.h>
#include <math.h>
#include <stdint.h>

using namespace nvcuda;

#define B_  32
#define N_  512
#define D_  512
#define H_  8
#define DK_ 64

// fp16 scratch (allocation-free rule: __device__ globals)
__device__ __half g_xh [B_*N_*D_];
__device__ __half g_wh [4*D_*D_];
__device__ __half g_qh [B_*H_*N_*DK_];
__device__ __half g_kh [B_*H_*N_*DK_];
__device__ __half g_vh [B_*H_*N_*DK_];
__device__ __half g_ctxh[B_*N_*D_];

__device__ __forceinline__ void st_half4(__half* p, float4 v) {
    __half2 a = __floats2half2_rn(v.x, v.y);
    __half2 b = __floats2half2_rn(v.z, v.w);
    uint2 u;
    u.x = *reinterpret_cast<uint32_t*>(&a);
    u.y = *reinterpret_cast<uint32_t*>(&b);
    *reinterpret_cast<uint2*>(p) = u;
}
__device__ __forceinline__ uint32_t smem_u32(const void* p) {
    uint32_t a;
    asm("{ .reg .u64 t; cvta.to.shared.u64 t, %1; cvt.u32.u64 %0, t; }" : "=r"(a) : "l"(p));
    return a;
}
#define CP_ASYNC16(dst, src) \
    asm volatile("cp.async.cg.shared.global [%0], [%1], 16;" :: "r"(dst), "l"(src))
#define CP_COMMIT() asm volatile("cp.async.commit_group;" ::: "memory")
#define CP_WAIT0()  asm volatile("cp.async.wait_group 0;" ::: "memory")
#define CP_WAIT1()  asm volatile("cp.async.wait_group 1;" ::: "memory")

// ---------------------------------------------------------------------------
// Prepass: convert x and the four weight matrices to fp16 once.
// ---------------------------------------------------------------------------
__global__ void conv_half(const float* __restrict__ x,
                          const float* __restrict__ Wq, const float* __restrict__ Wk,
                          const float* __restrict__ Wv, const float* __restrict__ Wo)
{
    const int XF4 = (B_ * N_ * D_) / 4;
    const int WF4 = (D_ * D_) / 4;
    const int i = blockIdx.x * blockDim.x + threadIdx.x;
    if (i < XF4) {
        st_half4(&g_xh[i * 4], reinterpret_cast<const float4*>(x)[i]);
    } else if (i < XF4 + 4 * WF4) {
        const int j = i - XF4;
        const int sel = j >> 16;
        const int off = j & (WF4 - 1);
        const float* W = sel == 0 ? Wq : sel == 1 ? Wk : sel == 2 ? Wv : Wo;
        st_half4(&g_wh[sel * D_ * D_ + off * 4],
                 reinterpret_cast<const float4*>(W)[off]);
    }
}

// ---------------------------------------------------------------------------
// fp16 wmma GEMM (round-8 proven config): 128 thr = 4 warps, warp tile 64x64,
// BK=32, 3-stage cp.async pipeline. Epilogue stage aliases the buffers.
// ---------------------------------------------------------------------------
#define GLD2 40
#define BUFB 10240                            // bytes per A (or B) stage buffer
#define GEMM_SMEM (128 * 132 * 4)             // 67584 >= 3*2*BUFB = 61440

template<int MODE>
__global__ __launch_bounds__(128, 2) void gemm_hc(
    const float* __restrict__ b0, const float* __restrict__ b1,
    const float* __restrict__ b2, float* __restrict__ outflat)
{
    extern __shared__ char smc[];
    float* stage = reinterpret_cast<float*>(smc);     // [128][132], epilogue only

    const int z = blockIdx.z;
    const __half* __restrict__ Ap = (MODE == 0) ? g_xh : g_ctxh;
    const __half* __restrict__ Wp = g_wh + (size_t)((MODE == 0) ? z : 3) * D_ * D_;
    const float*  __restrict__ bp = (MODE == 0) ? (z == 0 ? b0 : (z == 1 ? b1 : b2)) : b0;

    const int tid = threadIdx.x;
    const int w  = tid >> 5;
    const int wr = w >> 1;
    const int wc = w & 1;
    const int m0 = blockIdx.y * 128;
    const int n0 = blockIdx.x * 128;

    wmma::fragment<wmma::accumulator, 16, 16, 16, float> acc[4][4];
    #pragma unroll
    for (int mi = 0; mi < 4; mi++)
        #pragma unroll
        for (int ni = 0; ni < 4; ni++)
            wmma::fill_fragment(acc[mi][ni], 0.0f);

    const __half* arow = Ap + (size_t)(m0 + tid) * D_;
    const __half* brow = Wp + (size_t)(n0 + tid) * D_;
    uint32_t dA[3], dB[3];
    #pragma unroll
    for (int s = 0; s < 3; s++) {
        dA[s] = smem_u32(smc + s * 2 * BUFB) + tid * (GLD2 * 2);
        dB[s] = smem_u32(smc + s * 2 * BUFB + BUFB) + tid * (GLD2 * 2);
    }

    // prologue: chunks 0,1
    #pragma unroll
    for (int pc = 0; pc < 2; pc++) {
        #pragma unroll
        for (int c = 0; c < 4; c++) {
            CP_ASYNC16(dA[pc] + c * 16, arow + pc * 32 + c * 8);
            CP_ASYNC16(dB[pc] + c * 16, brow + pc * 32 + c * 8);
        }
        CP_COMMIT();
    }

    #pragma unroll 1
    for (int it = 0; it < 16; it++) {
        if (it == 15) { CP_WAIT0(); } else { CP_WAIT1(); }
        __syncthreads();

        if (it + 2 < 16) {
            const int s = (it + 2) % 3;
            const int kn = (it + 2) * 32;
            #pragma unroll
            for (int c = 0; c < 4; c++) {
                CP_ASYNC16(dA[s] + c * 16, arow + kn + c * 8);
                CP_ASYNC16(dB[s] + c * 16, brow + kn + c * 8);
            }
            CP_COMMIT();
        }

        const int cs = it % 3;
        const __half* bA = reinterpret_cast<const __half*>(smc + cs * 2 * BUFB);
        const __half* bB = reinterpret_cast<const __half*>(smc + cs * 2 * BUFB + BUFB);
        #pragma unroll
        for (int ks = 0; ks < 2; ks++) {
            wmma::fragment<wmma::matrix_a, 16, 16, 16, __half, wmma::row_major> af[4];
            wmma::fragment<wmma::matrix_b, 16, 16, 16, __half, wmma::col_major> bf[4];
            #pragma unroll
            for (int mi = 0; mi < 4; mi++)
                wmma::load_matrix_sync(af[mi], &bA[(wr * 64 + mi * 16) * GLD2 + ks * 16], GLD2);
            #pragma unroll
            for (int ni = 0; ni < 4; ni++)
                wmma::load_matrix_sync(bf[ni], &bB[(wc * 64 + ni * 16) * GLD2 + ks * 16], GLD2);
            #pragma unroll
            for (int mi = 0; mi < 4; mi++)
                #pragma unroll
                for (int ni = 0; ni < 4; ni++)
                    wmma::mma_sync(acc[mi][ni], af[mi], bf[ni], acc[mi][ni]);
        }
    }

    __syncthreads();   // computes done before stage overwrites buffers
    #pragma unroll
    for (int mi = 0; mi < 4; mi++)
        #pragma unroll
        for (int ni = 0; ni < 4; ni++)
            wmma::store_matrix_sync(&stage[(wr * 64 + mi * 16) * 132 + wc * 64 + ni * 16],
                                    acc[mi][ni], 132, wmma::mem_row_major);
    __syncthreads();

    const float scale = (MODE == 0 && z == 0) ? 0.125f : 1.0f;
    __half* dstH = (MODE == 0) ? (z == 0 ? g_qh : (z == 1 ? g_kh : g_vh)) : nullptr;

    for (int s = tid; s < 128 * 32; s += 128) {
        const int r  = s >> 5;
        const int c4 = s & 31;
        float4 v = *reinterpret_cast<const float4*>(&stage[r * 132 + c4 * 4]);
        const float4 bb = *reinterpret_cast<const float4*>(&bp[n0 + c4 * 4]);
        v.x = (v.x + bb.x) * scale;
        v.y = (v.y + bb.y) * scale;
        v.z = (v.z + bb.z) * scale;
        v.w = (v.w + bb.w) * scale;
        const int m = m0 + r;
        const int n = n0 + c4 * 4;
        if (MODE == 0) {
            const int batch = m >> 9;
            const int nn    = m & 511;
            const int h     = n >> 6;
            const int dk    = n & 63;
            st_half4(&dstH[(((size_t)batch * H_ + h) * N_ + nn) * DK_ + dk], v);
        } else {
            *reinterpret_cast<float4*>(&outflat[(size_t)m * D_ + n]) = v;
        }
    }
}

// ---------------------------------------------------------------------------
// Attention, fp16 wmma, shifted softmax (exact: constant shift cancels).
// O accumulator persists in register fragments; l-sum in thread registers.
// K/V double-buffered via cp.async. 3 barriers/tile (B4 removed: all arrays
// it protected are re-protected by B1/B2 of the next iteration).
// __launch_bounds__(256,3): 3 CTAs/SM (smem 73.2KB*3 fits 228KB carveout).
// ---------------------------------------------------------------------------
#define SLD 68
#define HLD 72
#define KVH (64 * HLD)
#define ATTN_SMEM ((64*SLD + 128) * 4 + 6 * KVH * 2)   // 73216

__global__ __launch_bounds__(256, 3) void attn_hc(
    const float* __restrict__ dist, const float* __restrict__ dw)
{
    extern __shared__ float sm[];
    float* Sf  = sm;                              // [64][SLD] scores / final O
    float* l_s = Sf + 64 * SLD;                   // [64]
    float* dws = l_s + 64;                        // [21..64]
    __half* Qs  = reinterpret_cast<__half*>(dws + 64);
    __half* Ps  = Qs + KVH;
    __half* Kb0 = Ps + KVH;
    __half* Vb0 = Kb0 + KVH;
    __half* Kb1 = Vb0 + KVH;
    __half* Vb1 = Kb1 + KVH;

    const int b  = blockIdx.z;
    const int h  = blockIdx.y;
    const int qt = blockIdx.x;
    const int tid = threadIdx.x;
    const int w  = tid >> 5;
    const int wm = w >> 1;
    const int wn = w & 1;
    const int q0 = qt * 64;
    const size_t base = ((size_t)b * H_ + h) * (size_t)N_ * DK_;

    if (tid < 21) dws[tid] = dw[tid];

    const uint32_t kd[2] = { smem_u32(Kb0), smem_u32(Kb1) };
    const uint32_t vd[2] = { smem_u32(Vb0), smem_u32(Vb1) };
    const int lrow0 = tid >> 3, lseg0 = tid & 7;
    const int lrow1 = (tid + 256) >> 3, lseg1 = tid & 7;

    {
        const __half* kg = g_kh + base;
        const __half* vg = g_vh + base;
        CP_ASYNC16(kd[0] + lrow0 * 144 + lseg0 * 16, kg + lrow0 * DK_ + lseg0 * 8);
        CP_ASYNC16(kd[0] + lrow1 * 144 + lseg1 * 16, kg + lrow1 * DK_ + lseg1 * 8);
        CP_ASYNC16(vd[0] + lrow0 * 144 + lseg0 * 16, vg + lrow0 * DK_ + lseg0 * 8);
        CP_ASYNC16(vd[0] + lrow1 * 144 + lseg1 * 16, vg + lrow1 * DK_ + lseg1 * 8);
        CP_COMMIT();
    }

    for (int s = tid; s < 64 * 16; s += 256) {
        const int r  = s >> 4;
        const int c4 = s & 15;
        *reinterpret_cast<uint2*>(&Qs[r * HLD + c4 * 4]) =
            *reinterpret_cast<const uint2*>(&g_qh[base + (size_t)(q0 + r) * DK_ + c4 * 4]);
    }
    __syncthreads();

    wmma::fragment<wmma::matrix_a, 16, 16, 16, __half, wmma::row_major> qf[4];
    #pragma unroll
    for (int d = 0; d < 4; d++)
        wmma::load_matrix_sync(qf[d], &Qs[(wm * 16) * HLD + d * 16], HLD);

    wmma::fragment<wmma::accumulator, 16, 16, 16, float> cacc[2];
    #pragma unroll
    for (int ni = 0; ni < 2; ni++) wmma::fill_fragment(cacc[ni], 0.0f);

    const int sr = tid >> 2;
    const int sp = tid & 3;
    float lsum = 0.0f;

    #pragma unroll 1
    for (int kt = 0; kt < 8; kt++) {
        CP_WAIT0();
        __syncthreads();                                  // B1: tile kt landed

        if (kt + 1 < 8) {
            const int nb = (kt + 1) & 1;
            const __half* kg = g_kh + base + (size_t)(kt + 1) * 64 * DK_;
            const __half* vg = g_vh + base + (size_t)(kt + 1) * 64 * DK_;
            CP_ASYNC16(kd[nb] + lrow0 * 144 + lseg0 * 16, kg + lrow0 * DK_ + lseg0 * 8);
            CP_ASYNC16(kd[nb] + lrow1 * 144 + lseg1 * 16, kg + lrow1 * DK_ + lseg1 * 8);
            CP_ASYNC16(vd[nb] + lrow0 * 144 + lseg0 * 16, vg + lrow0 * DK_ + lseg0 * 8);
            CP_ASYNC16(vd[nb] + lrow1 * 144 + lseg1 * 16, vg + lrow1 * DK_ + lseg1 * 8);
            CP_COMMIT();
        }

        const __half* Ks = (kt & 1) ? Kb1 : Kb0;
        const __half* Vs = (kt & 1) ? Vb1 : Vb0;

        // S = Q K^T -> Sf
        {
            wmma::fragment<wmma::accumulator, 16, 16, 16, float> sacc[2];
            #pragma unroll
            for (int ni = 0; ni < 2; ni++) wmma::fill_fragment(sacc[ni], 0.0f);
            #pragma unroll
            for (int d = 0; d < 4; d++) {
                wmma::fragment<wmma::matrix_b, 16, 16, 16, __half, wmma::col_major> bf[2];
                #pragma unroll
                for (int ni = 0; ni < 2; ni++)
                    wmma::load_matrix_sync(bf[ni], &Ks[(wn * 32 + ni * 16) * HLD + d * 16], HLD);
                #pragma unroll
                for (int ni = 0; ni < 2; ni++)
                    wmma::mma_sync(sacc[ni], qf[d], bf[ni], sacc[ni]);
            }
            #pragma unroll
            for (int ni = 0; ni < 2; ni++)
                wmma::store_matrix_sync(&Sf[(wm * 16) * SLD + wn * 32 + ni * 16],
                                        sacc[ni], SLD, wmma::mem_row_major);
        }
        __syncthreads();                                  // B2

        // P = exp(s + bias - 2)   (shifted softmax numerator, exact algebra)
        {
            const float* __restrict__ drow =
                &dist[((size_t)b * N_ + (q0 + sr)) * N_ + kt * 64 + sp * 16];
            #pragma unroll
            for (int i4 = 0; i4 < 4; i4++) {
                const float4 dd = *reinterpret_cast<const float4*>(&drow[i4 * 4]);
                const float4 ss = *reinterpret_cast<const float4*>(&Sf[sr * SLD + sp * 16 + i4 * 4]);
                int t0 = (int)(dd.x * 0.2f); t0 = t0 < 0 ? 0 : (t0 > 20 ? 20 : t0);
                int t1 = (int)(dd.y * 0.2f); t1 = t1 < 0 ? 0 : (t1 > 20 ? 20 : t1);
                int t2 = (int)(dd.z * 0.2f); t2 = t2 < 0 ? 0 : (t2 > 20 ? 20 : t2);
                int t3 = (int)(dd.w * 0.2f); t3 = t3 < 0 ? 0 : (t3 > 20 ? 20 : t3);
                float4 e;
                e.x = __expf(ss.x + dws[t0] - 2.0f);
                e.y = __expf(ss.y + dws[t1] - 2.0f);
                e.z = __expf(ss.z + dws[t2] - 2.0f);
                e.w = __expf(ss.w + dws[t3] - 2.0f);
                __half2 h0 = __floats2half2_rn(e.x, e.y);
                __half2 h1 = __floats2half2_rn(e.z, e.w);
                uint2 u;
                u.x = *reinterpret_cast<uint32_t*>(&h0);
                u.y = *reinterpret_cast<uint32_t*>(&h1);
                *reinterpret_cast<uint2*>(&Ps[sr * HLD + sp * 16 + i4 * 4]) = u;
                const float2 f0 = __half22float2(h0);
                const float2 f1 = __half22float2(h1);
                lsum += (f0.x + f0.y) + (f1.x + f1.y);
            }
        }
        __syncthreads();                                  // B3

        // O += P @ V   (cacc persists in registers; no trailing barrier —
        // next iteration's B1/B2 protect every array touched here)
        #pragma unroll
        for (int ks = 0; ks < 4; ks++) {
            wmma::fragment<wmma::matrix_a, 16, 16, 16, __half, wmma::row_major> pf;
            wmma::load_matrix_sync(pf, &Ps[(wm * 16) * HLD + ks * 16], HLD);
            wmma::fragment<wmma::matrix_b, 16, 16, 16, __half, wmma::row_major> vf[2];
            #pragma unroll
            for (int ni = 0; ni < 2; ni++)
                wmma::load_matrix_sync(vf[ni], &Vs[(ks * 16) * HLD + wn * 32 + ni * 16], HLD);
            #pragma unroll
            for (int ni = 0; ni < 2; ni++)
                wmma::mma_sync(cacc[ni], pf, vf[ni], cacc[ni]);
        }
    }

    lsum += __shfl_xor_sync(0xffffffffu, lsum, 1, 4);
    lsum += __shfl_xor_sync(0xffffffffu, lsum, 2, 4);
    if (sp == 0) l_s[sr] = lsum;

    #pragma unroll
    for (int ni = 0; ni < 2; ni++)
        wmma::store_matrix_sync(&Sf[(wm * 16) * SLD + wn * 32 + ni * 16],
                                cacc[ni], SLD, wmma::mem_row_major);
    __syncthreads();

    for (int s = tid; s < 64 * 16; s += 256) {
        const int r  = s >> 4;
        const int c4 = s & 15;
        const float inv = 1.0f / l_s[r];
        float4 o = *reinterpret_cast<const float4*>(&Sf[r * SLD + c4 * 4]);
        o.x *= inv; o.y *= inv; o.z *= inv; o.w *= inv;
        st_half4(&g_ctxh[((size_t)b * N_ + (q0 + r)) * D_ + h * 64 + c4 * 4], o);
    }
}

// ---------------------------------------------------------------------------
extern "C" void kernel_launch(void* const* d_in, const int* in_sizes, int n_in,
                              void* d_out, int out_size)
{
    const float* x    = (const float*)d_in[0];
    const float* dist = (const float*)d_in[1];
    const float* Wq   = (const float*)d_in[2];
    const float* bq   = (const float*)d_in[3];
    const float* Wk   = (const float*)d_in[4];
    const float* bk   = (const float*)d_in[5];
    const float* Wv   = (const float*)d_in[6];
    const float* bv   = (const float*)d_in[7];
    const float* Wo   = (const float*)d_in[8];
    const float* bo   = (const float*)d_in[9];
    const float* dw   = (const float*)d_in[10];
    float* out = (float*)d_out;

    cudaFuncSetAttribute(gemm_hc<0>, cudaFuncAttributeMaxDynamicSharedMemorySize, GEMM_SMEM);
    cudaFuncSetAttribute(gemm_hc<1>, cudaFuncAttributeMaxDynamicSharedMemorySize, GEMM_SMEM);
    cudaFuncSetAttribute(attn_hc,    cudaFuncAttributeMaxDynamicSharedMemorySize, ATTN_SMEM);

    const int convN = (B_*N_*D_)/4 + 4 * (D_*D_)/4;
    conv_half<<<(convN + 255) / 256, 256>>>(x, Wq, Wk, Wv, Wo);

    dim3 gridQKV(D_ / 128, (B_ * N_) / 128, 3);
    gemm_hc<0><<<gridQKV, 128, GEMM_SMEM>>>(bq, bk, bv, nullptr);

    dim3 gridAttn(N_ / 64, H_, B_);
    attn_hc<<<gridAttn, 256, ATTN_SMEM>>>(dist, dw);

    dim3 gridO(D_ / 128, (B_ * N_) / 128, 1);
    gemm_hc<1><<<gridO, 128, GEMM_SMEM>>>(bo, nullptr, nullptr, out);
}